// round 2
// baseline (speedup 1.0000x reference)
#include <cuda_runtime.h>
#include <stdint.h>

#define KOUT 49
#define MAXT 32
#define SAMPLES_PER_BLK 32
#define THREADS_PER_BLK 224              // 7 warps: warp w handles mu = w
#define XSTR 99                          // per-lane X blob: X1[0..48], X2[49..97], pad (99%32=3 odd -> conflict-free)
#define WBASE (SAMPLES_PER_BLK * XSTR)   // 3168 words
#define WSTR 29                          // per-thread W-half spill stride (29%32 odd -> conflict-free)
#define OBASE (WBASE + THREADS_PER_BLK * WSTR)  // 9664 words
#define OUTSTR 33
#define SMEM_WORDS (OBASE + KOUT * OUTSTR)      // 11281 words = 45124 B < 48KB static

// ---- device tables built by setup kernel each launch ----
__device__ int   g_T[8];             // stage1 term counts per mu; [7] = Ttot
__device__ int   g_TA[7], g_TB[7];   // stage2 split term counts per mup
__device__ uint4 g_s1[7 * MAXT];     // stage1: {x1_row_byteoff, x2_row_byteoff, c bits, pad}
__device__ uint2 g_s2a[7 * MAXT];    // stage2 half A (m2p<4): {Whalf_byteoff, d bits}
__device__ uint2 g_s2b[7 * MAXT];    // stage2 half B (m2p>=4)

// ---------------------------------------------------------------------------
// Setup: recover factorized term lists from the aligned product arrays.
// Generation order is (mu, t, mup, t'):
//   focc[v] (v<7)  -> start of (mu=0,t=0,mup=v) run ; focc[mu*7] -> mu segment
//   T[v] = focc[v+1]-focc[v] (v<6); T[6] = focc[7]/T[0] - focc[6]; Ttot = focc[6]+T[6]
// Coefficients from products only (A = mult[0] = c0^2):
//   c_hat(mu,t)   = mult[seg(mu) + t*Ttot]   (= c_t * c0)
//   d_hat(mup,t') = mult[focc[mup] + t'] / A (= c_t' / c0)   =>  c_hat*d_hat exact.
// Stage2 terms split by m2p<4 vs >=4 to match the two W column-half passes.
// ---------------------------------------------------------------------------
__global__ void wigner_setup(const float* __restrict__ mult,
                             const int* __restrict__ m1,  const int* __restrict__ m1p,
                             const int* __restrict__ m2,  const int* __restrict__ m2p,
                             const int* __restrict__ mub, int n)
{
    __shared__ int focc[KOUT];
    __shared__ int sT[8];
    int tid = threadIdx.x;
    if (tid < KOUT) focc[tid] = 0x7fffffff;
    __syncthreads();
    for (int j = tid; j < n; j += blockDim.x)
        atomicMin(&focc[mub[j]], j);
    __syncthreads();
    if (tid == 0) {
        int T0 = focc[1] - focc[0];
        sT[0] = T0;
        for (int v = 1; v < 6; v++) sT[v] = focc[v + 1] - focc[v];
        int t6 = focc[7] / T0 - focc[6];
        sT[6] = t6;
        sT[7] = focc[6] + t6;                       // Ttot
        for (int v = 0; v < 7; v++) if (sT[v] > MAXT) sT[v] = MAXT;
    }
    __syncthreads();
    if (tid < 8) g_T[tid] = sT[tid];
    float A = mult[0];
    int Ttot = sT[7];
    // stage1 table (parallel)
    if (tid < 7 * MAXT) {
        int mu = tid >> 5, t = tid & 31;
        if (t < sT[mu]) {
            int j = focc[mu * 7] + t * Ttot;
            g_s1[tid] = make_uint4((unsigned)(m1[j] * 28),
                                   (unsigned)(196 + m2[j] * 28),
                                   __float_as_uint(mult[j]), 0u);
        }
    }
    // stage2 split lists (serial per mup; T <= 32, trivial)
    if (tid < 7) {
        int mup = tid, na = 0, nb = 0;
        for (int t = 0; t < sT[mup]; t++) {
            int j2 = focc[mup] + t;
            float d = mult[j2] / A;
            int a = m1p[j2], b = m2p[j2];
            if (b < 4) g_s2a[mup * MAXT + na++] =
                make_uint2((unsigned)((a * 4 + b) * 4), __float_as_uint(d));
            else       g_s2b[mup * MAXT + nb++] =
                make_uint2((unsigned)((a * 3 + b - 4) * 4), __float_as_uint(d));
        }
        g_TA[mup] = na; g_TB[mup] = nb;
    }
}

// ---------------------------------------------------------------------------
// Main: thread = (sample, mu). 7 warps/block, warp w -> mu = w, lane -> sample.
// W computed in two column-halves (28 + 21 regs), each spilled to a 29-word
// per-thread shared slot for the dynamic stage-2 gather; 7 persistent
// accumulators collect both halves. Only syncs: after X stage-in, before flush.
// ---------------------------------------------------------------------------
__global__ void __launch_bounds__(THREADS_PER_BLK, 4)
wigner_main(const float* __restrict__ X1, const float* __restrict__ X2,
            float* __restrict__ out, int N)
{
    __shared__ float sm[SMEM_WORDS];
    int tid  = threadIdx.x;
    int lane = tid & 31;
    int mu   = tid >> 5;
    int base = blockIdx.x * SAMPLES_PER_BLK;
    int nvalid = N - base; if (nvalid > SAMPLES_PER_BLK) nvalid = SAMPLES_PER_BLK;
    int total = nvalid * KOUT;

    const float* g1 = X1 + (size_t)base * KOUT;
    const float* g2 = X2 + (size_t)base * KOUT;

    // stage in: coalesced global -> per-lane blobs
    for (int i = tid; i < total; i += THREADS_PER_BLK) {
        int s = i / KOUT;
        int c = i - s * KOUT;
        sm[s * XSTR + c]      = g1[i];
        sm[s * XSTR + 49 + c] = g2[i];
    }
    __syncthreads();

    if (lane < nvalid) {
        const char* xc = (const char*)(sm + lane * XSTR);
        float*      wp = sm + WBASE + tid * WSTR;
        const char* wc = (const char*)wp;

        int Tmu = __ldg(&g_T[mu]);
        const uint4* s1 = g_s1 + mu * MAXT;
        float acc[7];
        #pragma unroll
        for (int q = 0; q < 7; q++) acc[q] = 0.0f;

        // ---------------- PASS A : W columns b = 0..3 ----------------
        {
            float W[28];
            #pragma unroll
            for (int i = 0; i < 28; i++) W[i] = 0.0f;
            #pragma unroll 2
            for (int t = 0; t < Tmu; t++) {
                uint4 e = __ldg(&s1[t]);                  // warp-uniform broadcast
                float c = __uint_as_float(e.z);
                const float* r1 = (const float*)(xc + e.x);
                const float* r2 = (const float*)(xc + e.y);
                float x2v[4];
                #pragma unroll
                for (int b = 0; b < 4; b++) x2v[b] = r2[b];
                #pragma unroll
                for (int a = 0; a < 7; a++) {
                    float t1 = c * r1[a];
                    #pragma unroll
                    for (int b = 0; b < 4; b++)
                        W[a * 4 + b] = fmaf(t1, x2v[b], W[a * 4 + b]);
                }
            }
            #pragma unroll
            for (int i = 0; i < 28; i++) wp[i] = W[i];
            #pragma unroll 1
            for (int mup = 0; mup < 7; mup++) {
                const uint2* s2 = g_s2a + mup * MAXT;
                int Tp = __ldg(&g_TA[mup]);
                float a0 = 0.0f, a1 = 0.0f;
                int tp = 0;
                for (; tp + 2 <= Tp; tp += 2) {
                    uint2 e0 = __ldg(&s2[tp]);
                    uint2 e1 = __ldg(&s2[tp + 1]);
                    a0 = fmaf(__uint_as_float(e0.y), *(const float*)(wc + e0.x), a0);
                    a1 = fmaf(__uint_as_float(e1.y), *(const float*)(wc + e1.x), a1);
                }
                if (tp < Tp) {
                    uint2 e0 = __ldg(&s2[tp]);
                    a0 = fmaf(__uint_as_float(e0.y), *(const float*)(wc + e0.x), a0);
                }
                acc[mup] += a0 + a1;
            }
        }

        // ---------------- PASS B : W columns b = 4..6 ----------------
        {
            float W[21];
            #pragma unroll
            for (int i = 0; i < 21; i++) W[i] = 0.0f;
            #pragma unroll 2
            for (int t = 0; t < Tmu; t++) {
                uint4 e = __ldg(&s1[t]);
                float c = __uint_as_float(e.z);
                const float* r1 = (const float*)(xc + e.x);
                const float* r2 = (const float*)(xc + e.y);
                float x2v[3];
                #pragma unroll
                for (int b = 0; b < 3; b++) x2v[b] = r2[4 + b];
                #pragma unroll
                for (int a = 0; a < 7; a++) {
                    float t1 = c * r1[a];
                    #pragma unroll
                    for (int b = 0; b < 3; b++)
                        W[a * 3 + b] = fmaf(t1, x2v[b], W[a * 3 + b]);
                }
            }
            #pragma unroll
            for (int i = 0; i < 21; i++) wp[i] = W[i];
            #pragma unroll 1
            for (int mup = 0; mup < 7; mup++) {
                const uint2* s2 = g_s2b + mup * MAXT;
                int Tp = __ldg(&g_TB[mup]);
                float a0 = 0.0f, a1 = 0.0f;
                int tp = 0;
                for (; tp + 2 <= Tp; tp += 2) {
                    uint2 e0 = __ldg(&s2[tp]);
                    uint2 e1 = __ldg(&s2[tp + 1]);
                    a0 = fmaf(__uint_as_float(e0.y), *(const float*)(wc + e0.x), a0);
                    a1 = fmaf(__uint_as_float(e1.y), *(const float*)(wc + e1.x), a1);
                }
                if (tp < Tp) {
                    uint2 e0 = __ldg(&s2[tp]);
                    a0 = fmaf(__uint_as_float(e0.y), *(const float*)(wc + e0.x), a0);
                }
                acc[mup] += a0 + a1;
            }
        }

        // stage output transposed (conflict-free: consecutive words per warp)
        #pragma unroll
        for (int mup = 0; mup < 7; mup++)
            sm[OBASE + (mu * 7 + mup) * OUTSTR + lane] = acc[mup];
    }
    __syncthreads();

    // coalesced flush
    float* go = out + (size_t)base * KOUT;
    for (int i = tid; i < total; i += THREADS_PER_BLK) {
        int s = i / KOUT;
        int c = i - s * KOUT;
        go[i] = sm[OBASE + c * OUTSTR + s];
    }
}

// ---------------------------------------------------------------------------
extern "C" void kernel_launch(void* const* d_in, const int* in_sizes, int n_in,
                              void* d_out, int out_size)
{
    const float* X1   = (const float*)d_in[0];
    const float* X2   = (const float*)d_in[1];
    const float* mult = (const float*)d_in[2];
    const int*   m1   = (const int*)d_in[3];
    const int*   m1p  = (const int*)d_in[4];
    const int*   m2   = (const int*)d_in[5];
    const int*   m2p  = (const int*)d_in[6];
    const int*   mub  = (const int*)d_in[7];

    int n_aligned = in_sizes[2];
    int N = in_sizes[0] / KOUT;

    wigner_setup<<<1, 256>>>(mult, m1, m1p, m2, m2p, mub, n_aligned);

    int grid = (N + SAMPLES_PER_BLK - 1) / SAMPLES_PER_BLK;
    wigner_main<<<grid, THREADS_PER_BLK>>>(X1, X2, (float*)d_out, N);
}

// round 3
// speedup vs baseline: 1.1618x; 1.1618x over previous
#include <cuda_runtime.h>
#include <stdint.h>

#define KOUT 49
#define MAXT 32
#define SAMPLES_PER_BLK 32
#define THREADS_PER_BLK 224              // 7 warps: warp w handles mu = w, lane = sample
#define XSTR 99                          // per-lane X blob: X1[0..48], X2[49..97], pad (odd -> conflict-free)
#define OBASE (SAMPLES_PER_BLK * XSTR)   // 3168 words
#define OUTSTR 33
#define SMEM_WORDS (OBASE + KOUT * OUTSTR)   // 4785 words = 19140 B

// ---- device tables built by setup kernel each launch ----
__device__ int   g_T[8];             // stage1 term counts per mu; [7] = Ttot
__device__ uint4 g_s1[7 * MAXT];     // stage1: {x1_row_byteoff, x2_row_byteoff, c bits, pad}
__device__ uint2 g_s2[7 * MAXT];     // stage2: {W_byteoff, d bits}

// ---------------------------------------------------------------------------
// Setup: recover factorized term lists from the aligned product arrays.
// Generation order is (mu, t, mup, t'):
//   focc[v] (v<7)  -> start of (mu=0,t=0,mup=v) run ; focc[mu*7] -> mu segment
//   T[v] = focc[v+1]-focc[v] (v<6); T[6] = focc[7]/T[0] - focc[6]; Ttot = focc[6]+T[6]
// Coefficients from products only (A = mult[0] = c0^2):
//   c_hat(mu,t)   = mult[seg(mu) + t*Ttot]   (= c_t * c0)
//   d_hat(mup,t') = mult[focc[mup] + t'] / A (= c_t' / c0)   =>  c_hat*d_hat exact.
// ---------------------------------------------------------------------------
__global__ void wigner_setup(const float* __restrict__ mult,
                             const int* __restrict__ m1,  const int* __restrict__ m1p,
                             const int* __restrict__ m2,  const int* __restrict__ m2p,
                             const int* __restrict__ mub, int n)
{
    __shared__ int focc[KOUT];
    __shared__ int sT[8];
    int tid = threadIdx.x;
    if (tid < KOUT) focc[tid] = 0x7fffffff;
    __syncthreads();
    for (int j = tid; j < n; j += blockDim.x)
        atomicMin(&focc[mub[j]], j);
    __syncthreads();
    if (tid == 0) {
        int T0 = focc[1] - focc[0];
        sT[0] = T0;
        for (int v = 1; v < 6; v++) sT[v] = focc[v + 1] - focc[v];
        int t6 = focc[7] / T0 - focc[6];
        sT[6] = t6;
        sT[7] = focc[6] + t6;                       // Ttot
        for (int v = 0; v < 7; v++) if (sT[v] > MAXT) sT[v] = MAXT;
    }
    __syncthreads();
    if (tid < 8) g_T[tid] = sT[tid];
    float A = mult[0];
    int Ttot = sT[7];
    if (tid < 7 * MAXT) {
        int mu = tid >> 5, t = tid & 31;
        if (t < sT[mu]) {
            int j = focc[mu * 7] + t * Ttot;               // (mu, t, mup=0, t'=0)
            g_s1[tid] = make_uint4((unsigned)(m1[j] * 28),
                                   (unsigned)(196 + m2[j] * 28),
                                   __float_as_uint(mult[j]), 0u);
            int j2 = focc[mu] + t;                          // (mu=0, t=0, mup, t')
            g_s2[tid] = make_uint2((unsigned)((m1p[j2] * 7 + m2p[j2]) * 4),
                                   __float_as_uint(mult[j2] / A));
        } else {
            g_s1[tid] = make_uint4(0u, 196u, 0u, 0u);
            g_s2[tid] = make_uint2(0u, 0u);
        }
    }
}

// ---------------------------------------------------------------------------
// Main: thread = (sample, mu). 7 warps/block, warp w -> mu = w, lane -> sample.
// Single-pass stage-1 accumulates W[49] in registers; W is then spilled to
// per-thread LOCAL memory (lane-interleaved -> warp-uniform gather offsets are
// perfectly coalesced 128B L1 accesses, zero smem cost). Stage-2 gathers with
// 4 accumulators to cover LDL latency. Term tables live in shared (broadcast).
// ---------------------------------------------------------------------------
__global__ void __launch_bounds__(THREADS_PER_BLK, 3)
wigner_main(const float* __restrict__ X1, const float* __restrict__ X2,
            float* __restrict__ out, int N)
{
    __shared__ float sm[SMEM_WORDS];
    __shared__ uint4 s_s1[7 * MAXT];
    __shared__ uint2 s_s2[7 * MAXT];
    __shared__ int   s_T[8];

    int tid  = threadIdx.x;
    int lane = tid & 31;
    int mu   = tid >> 5;
    int base = blockIdx.x * SAMPLES_PER_BLK;
    int nvalid = N - base; if (nvalid > SAMPLES_PER_BLK) nvalid = SAMPLES_PER_BLK;
    int total = nvalid * KOUT;

    // copy tables into shared (one entry per thread)
    s_s1[tid] = g_s1[tid];
    s_s2[tid] = g_s2[tid];
    if (tid < 8) s_T[tid] = g_T[tid];

    const float* g1 = X1 + (size_t)base * KOUT;
    const float* g2 = X2 + (size_t)base * KOUT;

    // stage in: coalesced global -> per-lane blobs
    for (int i = tid; i < total; i += THREADS_PER_BLK) {
        int s = i / KOUT;
        int c = i - s * KOUT;
        sm[s * XSTR + c]      = g1[i];
        sm[s * XSTR + 49 + c] = g2[i];
    }
    __syncthreads();

    if (lane < nvalid) {
        const char* xc = (const char*)(sm + lane * XSTR);

        // ---------------- stage 1 : W[49] in registers, single pass ----------
        float W[49];
        #pragma unroll
        for (int i = 0; i < 49; i++) W[i] = 0.0f;

        int Tmu = s_T[mu];
        const uint4* s1 = s_s1 + mu * MAXT;
        for (int t = 0; t < Tmu; t++) {
            uint4 e = s1[t];                          // LDS.128 broadcast
            float c = __uint_as_float(e.z);
            const float* r1 = (const float*)(xc + e.x);
            const float* r2 = (const float*)(xc + e.y);
            float x2v[7];
            #pragma unroll
            for (int b = 0; b < 7; b++) x2v[b] = r2[b];
            #pragma unroll
            for (int a = 0; a < 7; a++) {
                float t1 = c * r1[a];
                #pragma unroll
                for (int b = 0; b < 7; b++)
                    W[a * 7 + b] = fmaf(t1, x2v[b], W[a * 7 + b]);
            }
        }

        // spill to per-thread local memory (dynamic reads below keep it there)
        float ws[49];
        #pragma unroll
        for (int i = 0; i < 49; i++) ws[i] = W[i];
        const char* wc = (const char*)ws;

        // ---------------- stage 2 : sparse gather, 4 accumulators ------------
        #pragma unroll 1
        for (int mup = 0; mup < 7; mup++) {
            const uint2* s2 = s_s2 + mup * MAXT;
            int Tp = s_T[mup];
            float a0 = 0.0f, a1 = 0.0f, a2 = 0.0f, a3 = 0.0f;
            int tp = 0;
            for (; tp + 4 <= Tp; tp += 4) {
                uint2 e0 = s2[tp];
                uint2 e1 = s2[tp + 1];
                uint2 e2 = s2[tp + 2];
                uint2 e3 = s2[tp + 3];
                a0 = fmaf(__uint_as_float(e0.y), *(const float*)(wc + e0.x), a0);
                a1 = fmaf(__uint_as_float(e1.y), *(const float*)(wc + e1.x), a1);
                a2 = fmaf(__uint_as_float(e2.y), *(const float*)(wc + e2.x), a2);
                a3 = fmaf(__uint_as_float(e3.y), *(const float*)(wc + e3.x), a3);
            }
            for (; tp < Tp; tp++) {
                uint2 e0 = s2[tp];
                a0 = fmaf(__uint_as_float(e0.y), *(const float*)(wc + e0.x), a0);
            }
            sm[OBASE + (mu * 7 + mup) * OUTSTR + lane] = (a0 + a1) + (a2 + a3);
        }
    }
    __syncthreads();

    // coalesced flush (conflict-free: stride 33 is odd)
    float* go = out + (size_t)base * KOUT;
    for (int i = tid; i < total; i += THREADS_PER_BLK) {
        int s = i / KOUT;
        int c = i - s * KOUT;
        go[i] = sm[OBASE + c * OUTSTR + s];
    }
}

// ---------------------------------------------------------------------------
extern "C" void kernel_launch(void* const* d_in, const int* in_sizes, int n_in,
                              void* d_out, int out_size)
{
    const float* X1   = (const float*)d_in[0];
    const float* X2   = (const float*)d_in[1];
    const float* mult = (const float*)d_in[2];
    const int*   m1   = (const int*)d_in[3];
    const int*   m1p  = (const int*)d_in[4];
    const int*   m2   = (const int*)d_in[5];
    const int*   m2p  = (const int*)d_in[6];
    const int*   mub  = (const int*)d_in[7];

    int n_aligned = in_sizes[2];
    int N = in_sizes[0] / KOUT;

    wigner_setup<<<1, 256>>>(mult, m1, m1p, m2, m2p, mub, n_aligned);

    int grid = (N + SAMPLES_PER_BLK - 1) / SAMPLES_PER_BLK;
    wigner_main<<<grid, THREADS_PER_BLK>>>(X1, X2, (float*)d_out, N);
}

// round 4
// speedup vs baseline: 1.5524x; 1.3361x over previous
#include <cuda_runtime.h>
#include <stdint.h>

#define KOUT 49
#define MAXT 32
#define SAMPLES_PER_BLK 32
#define THREADS_PER_BLK 224              // 7 warps: warp w handles mu = w, lane = sample
#define XSTR 99                          // per-lane X blob: X1[0..48], X2[49..97], pad (odd -> conflict-free)
#define OBASE (SAMPLES_PER_BLK * XSTR)   // 3168 words
#define OUTSTR 33
#define SMEM_WORDS (OBASE + KOUT * OUTSTR)   // 4785 words = 19140 B

// ---- device tables built by setup kernel each launch ----
__device__ int   g_T[8];             // [0..6] stage1 term counts per mu; [7] = max over mu (padded stage2 bound)
__device__ uint4 g_s1[7 * MAXT];     // stage1: {x1_row_byteoff, x2_row_byteoff, c bits, pad}
__device__ uint2 g_s2[7 * MAXT];     // stage2: {W_byteoff, d bits}; zero-padded to MAXT

// ---------------------------------------------------------------------------
// Setup: recover factorized term lists from the aligned product arrays.
// Generation order is (mu, t, mup, t'):
//   focc[v] (v<7)  -> start of (mu=0,t=0,mup=v) run ; focc[mu*7] -> mu segment
//   T[v] = focc[v+1]-focc[v] (v<6); T[6] = focc[7]/T[0] - focc[6]; Ttot = focc[6]+T[6]
// Coefficients from products only (A = mult[0] = c0^2):
//   c_hat(mu,t)   = mult[seg(mu) + t*Ttot]   (= c_t * c0)
//   d_hat(mup,t') = mult[focc[mup] + t'] / A (= c_t' / c0)   =>  c_hat*d_hat exact.
// ---------------------------------------------------------------------------
__global__ void wigner_setup(const float* __restrict__ mult,
                             const int* __restrict__ m1,  const int* __restrict__ m1p,
                             const int* __restrict__ m2,  const int* __restrict__ m2p,
                             const int* __restrict__ mub, int n)
{
    __shared__ int focc[KOUT];
    __shared__ int sT[8];
    int tid = threadIdx.x;
    if (tid < KOUT) focc[tid] = 0x7fffffff;
    __syncthreads();
    for (int j = tid; j < n; j += blockDim.x)
        atomicMin(&focc[mub[j]], j);
    __syncthreads();
    if (tid == 0) {
        int T0 = focc[1] - focc[0];
        sT[0] = T0;
        for (int v = 1; v < 6; v++) sT[v] = focc[v + 1] - focc[v];
        int t6 = focc[7] / T0 - focc[6];
        sT[6] = t6;
        sT[7] = focc[6] + t6;                       // Ttot (setup-internal)
        for (int v = 0; v < 7; v++) if (sT[v] > MAXT) sT[v] = MAXT;
    }
    __syncthreads();
    if (tid < 7) g_T[tid] = sT[tid];
    if (tid == 0) {
        int mx = 0;
        for (int v = 0; v < 7; v++) if (sT[v] > mx) mx = sT[v];
        g_T[7] = mx;                                // padded stage-2 loop bound
    }
    float A = mult[0];
    int Ttot = sT[7];
    if (tid < 7 * MAXT) {
        int mu = tid >> 5, t = tid & 31;
        if (t < sT[mu]) {
            int j = focc[mu * 7] + t * Ttot;               // (mu, t, mup=0, t'=0)
            g_s1[tid] = make_uint4((unsigned)(m1[j] * 28),
                                   (unsigned)(196 + m2[j] * 28),
                                   __float_as_uint(mult[j]), 0u);
            int j2 = focc[mu] + t;                          // (mu=0, t=0, mup, t')
            g_s2[tid] = make_uint2((unsigned)((m1p[j2] * 7 + m2p[j2]) * 4),
                                   __float_as_uint(mult[j2] / A));
        } else {
            g_s1[tid] = make_uint4(0u, 196u, 0u, 0u);
            g_s2[tid] = make_uint2(0u, 0u);                 // pad: fmaf(0, ws[0], acc) is a no-op
        }
    }
}

// ---------------------------------------------------------------------------
// Main: thread = (sample, mu). 7 warps/block, warp w -> mu = w, lane -> sample.
// KEY FIX vs R3: staging issues all 14 LDG up-front (MLP=14, one DRAM wait
// instead of 7 serialized ~600-cyc round trips). Stage-2 runs all 7 mup
// gather chains interleaved (7 independent LDS->LDL->FMA chains) over a
// zero-padded uniform bound. Stage-1 table entry is double-buffered.
// ---------------------------------------------------------------------------
__global__ void __launch_bounds__(THREADS_PER_BLK, 3)
wigner_main(const float* __restrict__ X1, const float* __restrict__ X2,
            float* __restrict__ out, int N)
{
    __shared__ float sm[SMEM_WORDS];
    __shared__ uint4 s_s1[7 * MAXT];
    __shared__ uint2 s_s2[7 * MAXT];
    __shared__ int   s_T[8];

    int tid  = threadIdx.x;
    int lane = tid & 31;
    int mu   = tid >> 5;
    int base = blockIdx.x * SAMPLES_PER_BLK;
    int nvalid = N - base; if (nvalid > SAMPLES_PER_BLK) nvalid = SAMPLES_PER_BLK;

    const float* g1 = X1 + (size_t)base * KOUT;
    const float* g2 = X2 + (size_t)base * KOUT;

    // ---- staging: batched LDG (MLP=14) then STS; fast path for full blocks
    if (nvalid == SAMPLES_PER_BLK) {
        float r1v[7], r2v[7];
        #pragma unroll
        for (int k = 0; k < 7; k++) {
            int i = tid + k * THREADS_PER_BLK;
            r1v[k] = g1[i];
            r2v[k] = g2[i];
        }
        // overlap table copy with the in-flight loads
        s_s1[tid] = g_s1[tid];
        s_s2[tid] = g_s2[tid];
        if (tid < 8) s_T[tid] = g_T[tid];
        #pragma unroll
        for (int k = 0; k < 7; k++) {
            int i = tid + k * THREADS_PER_BLK;
            int s = i / KOUT;
            int c = i - s * KOUT;
            sm[s * XSTR + c]      = r1v[k];
            sm[s * XSTR + 49 + c] = r2v[k];
        }
    } else {
        s_s1[tid] = g_s1[tid];
        s_s2[tid] = g_s2[tid];
        if (tid < 8) s_T[tid] = g_T[tid];
        int total = nvalid * KOUT;
        for (int i = tid; i < total; i += THREADS_PER_BLK) {
            int s = i / KOUT;
            int c = i - s * KOUT;
            sm[s * XSTR + c]      = g1[i];
            sm[s * XSTR + 49 + c] = g2[i];
        }
    }
    __syncthreads();

    if (lane < nvalid) {
        const char* xc = (const char*)(sm + lane * XSTR);

        // ---------------- stage 1 : W[49] in registers, single pass ----------
        float W[49];
        #pragma unroll
        for (int i = 0; i < 49; i++) W[i] = 0.0f;

        int Tmu = s_T[mu];
        const uint4* s1 = s_s1 + mu * MAXT;
        uint4 e = s1[0];                              // double-buffered table entry
        for (int t = 0; t < Tmu; t++) {
            uint4 en = s1[t + 1];                     // prefetch next (pad-safe)
            float c = __uint_as_float(e.z);
            const float* r1 = (const float*)(xc + e.x);
            const float* r2 = (const float*)(xc + e.y);
            float x2v[7];
            #pragma unroll
            for (int b = 0; b < 7; b++) x2v[b] = r2[b];
            #pragma unroll
            for (int a = 0; a < 7; a++) {
                float t1 = c * r1[a];
                #pragma unroll
                for (int b = 0; b < 7; b++)
                    W[a * 7 + b] = fmaf(t1, x2v[b], W[a * 7 + b]);
            }
            e = en;
        }

        // spill to per-thread local memory (warp-uniform gather offsets below
        // hit lane-interleaved local -> perfectly coalesced L1 accesses)
        float ws[49];
        #pragma unroll
        for (int i = 0; i < 49; i++) ws[i] = W[i];
        const char* wc = (const char*)ws;

        // ---------------- stage 2 : 7 interleaved gather chains --------------
        float acc[7];
        #pragma unroll
        for (int q = 0; q < 7; q++) acc[q] = 0.0f;

        int Tpmax = s_T[7];
        #pragma unroll 2
        for (int tp = 0; tp < Tpmax; tp++) {
            #pragma unroll
            for (int mup = 0; mup < 7; mup++) {
                uint2 t2 = s_s2[mup * MAXT + tp];     // zero-padded beyond T[mup]
                acc[mup] = fmaf(__uint_as_float(t2.y),
                                *(const float*)(wc + t2.x), acc[mup]);
            }
        }

        // stage output transposed (conflict-free: stride 33 odd)
        #pragma unroll
        for (int mup = 0; mup < 7; mup++)
            sm[OBASE + (mu * 7 + mup) * OUTSTR + lane] = acc[mup];
    }
    __syncthreads();

    // coalesced flush (STG fire-and-forget)
    int total = nvalid * KOUT;
    float* go = out + (size_t)base * KOUT;
    for (int i = tid; i < total; i += THREADS_PER_BLK) {
        int s = i / KOUT;
        int c = i - s * KOUT;
        go[i] = sm[OBASE + c * OUTSTR + s];
    }
}

// ---------------------------------------------------------------------------
extern "C" void kernel_launch(void* const* d_in, const int* in_sizes, int n_in,
                              void* d_out, int out_size)
{
    const float* X1   = (const float*)d_in[0];
    const float* X2   = (const float*)d_in[1];
    const float* mult = (const float*)d_in[2];
    const int*   m1   = (const int*)d_in[3];
    const int*   m1p  = (const int*)d_in[4];
    const int*   m2   = (const int*)d_in[5];
    const int*   m2p  = (const int*)d_in[6];
    const int*   mub  = (const int*)d_in[7];

    int n_aligned = in_sizes[2];
    int N = in_sizes[0] / KOUT;

    wigner_setup<<<1, 256>>>(mult, m1, m1p, m2, m2p, mub, n_aligned);

    int grid = (N + SAMPLES_PER_BLK - 1) / SAMPLES_PER_BLK;
    wigner_main<<<grid, THREADS_PER_BLK>>>(X1, X2, (float*)d_out, N);
}